// round 2
// baseline (speedup 1.0000x reference)
#include <cuda_runtime.h>
#include <math.h>

#define BATCH 8
#define TD 256
#define TE 256
#define DIN 80
#define D 512
#define MEL 80
#define ROWS (BATCH*TD)          // 2048
#define NBLK_LSTM 128

// ----------------------------- scratch (device globals) ---------------------
__device__ __align__(16) float g_Xg[ROWS * 4 * D];        // inputs@Wk + b : [2048][2048]
__device__ __align__(16) float g_h1[ROWS * D];            // attended@W1+b1: [2048][512]
__device__ __align__(16) float g_h2[ROWS * D];            // x@W1+b1      : [2048][512]
__device__ __align__(16) float g_XC[ROWS * 2 * D];        // [x | weighted]: [2048][1024]
__device__ __align__(16) float g_scores[BATCH * TD * TE]; // scores/attn   : [2048][256]
__device__ __align__(16) float g_hbuf[2][BATCH * D];      // double-buffered h
__device__ unsigned g_count;
__device__ volatile unsigned g_gen;

// ----------------------------- helpers --------------------------------------
__device__ __forceinline__ float fast_tanh(float x) {
    float y;
    asm("tanh.approx.f32 %0, %1;" : "=f"(y) : "f"(x));
    return y;
}

__device__ __forceinline__ void grid_barrier(unsigned nblocks) {
    __syncthreads();
    if (threadIdx.x == 0) {
        unsigned gen = g_gen;
        __threadfence();
        if (atomicAdd(&g_count, 1u) == nblocks - 1) {
            g_count = 0;
            __threadfence();
            g_gen = gen + 1;
        } else {
            while (g_gen == gen) { __nanosleep(64); }
            __threadfence();
        }
    }
    __syncthreads();
}

// ----------------------------- generic tiled SGEMM --------------------------
// C[M,N] = A[M,K] @ B[K,N] (+ bias[N]).  64x64 tile, BK=16, 256 thr, 4x4 micro.
__global__ void __launch_bounds__(256) sgemm_kernel(
    const float* __restrict__ A, int lda, long sA,
    const float* __restrict__ B, int ldb, long sB,
    float* __restrict__ C, int ldc, long sC,
    int M, int N, int K, const float* __restrict__ bias)
{
    __shared__ float As[64 * 16];   // [m][k]
    __shared__ float Bs[16 * 64];   // [k][n]
    const int tid = threadIdx.x;
    const int tx = tid & 15, ty = tid >> 4;
    const int m0 = blockIdx.y << 6, n0 = blockIdx.x << 6;
    A += (long)blockIdx.z * sA;
    B += (long)blockIdx.z * sB;
    C += (long)blockIdx.z * sC;

    const int aRow = tid >> 2, aCol = (tid & 3) << 2;   // A loader
    const int bRow = tid >> 4, bCol = (tid & 15) << 2;  // B loader

    float acc[4][4];
#pragma unroll
    for (int i = 0; i < 4; i++)
#pragma unroll
        for (int j = 0; j < 4; j++) acc[i][j] = 0.f;

    for (int k0 = 0; k0 < K; k0 += 16) {
        float4 av = make_float4(0.f, 0.f, 0.f, 0.f);
        if (m0 + aRow < M && k0 + aCol + 3 < K) {
            av = *(const float4*)&A[(long)(m0 + aRow) * lda + k0 + aCol];
        } else if (m0 + aRow < M) {
            float* p = (float*)&av;
#pragma unroll
            for (int c = 0; c < 4; c++)
                if (k0 + aCol + c < K) p[c] = A[(long)(m0 + aRow) * lda + k0 + aCol + c];
        }
        *(float4*)&As[aRow * 16 + aCol] = av;

        float4 bv = make_float4(0.f, 0.f, 0.f, 0.f);
        if (k0 + bRow < K && n0 + bCol + 3 < N) {
            bv = *(const float4*)&B[(long)(k0 + bRow) * ldb + n0 + bCol];
        } else if (k0 + bRow < K) {
            float* p = (float*)&bv;
#pragma unroll
            for (int c = 0; c < 4; c++)
                if (n0 + bCol + c < N) p[c] = B[(long)(k0 + bRow) * ldb + n0 + bCol + c];
        }
        *(float4*)&Bs[bRow * 64 + bCol] = bv;
        __syncthreads();

#pragma unroll
        for (int k = 0; k < 16; k++) {
            float a0 = As[(ty * 4 + 0) * 16 + k];
            float a1 = As[(ty * 4 + 1) * 16 + k];
            float a2 = As[(ty * 4 + 2) * 16 + k];
            float a3 = As[(ty * 4 + 3) * 16 + k];
            float4 b4 = *(const float4*)&Bs[k * 64 + tx * 4];
            acc[0][0] += a0 * b4.x; acc[0][1] += a0 * b4.y; acc[0][2] += a0 * b4.z; acc[0][3] += a0 * b4.w;
            acc[1][0] += a1 * b4.x; acc[1][1] += a1 * b4.y; acc[1][2] += a1 * b4.z; acc[1][3] += a1 * b4.w;
            acc[2][0] += a2 * b4.x; acc[2][1] += a2 * b4.y; acc[2][2] += a2 * b4.z; acc[2][3] += a2 * b4.w;
            acc[3][0] += a3 * b4.x; acc[3][1] += a3 * b4.y; acc[3][2] += a3 * b4.z; acc[3][3] += a3 * b4.w;
        }
        __syncthreads();
    }

#pragma unroll
    for (int i = 0; i < 4; i++) {
        int m = m0 + ty * 4 + i;
        if (m >= M) continue;
#pragma unroll
        for (int j = 0; j < 4; j++) {
            int n = n0 + tx * 4 + j;
            if (n < N) {
                float v = acc[i][j];
                if (bias) v += bias[n];
                C[(long)m * ldc + n] = v;
            }
        }
    }
}

// ----------------------------- persistent LSTM ------------------------------
// 128 CTAs x 256 threads. CTA g owns hidden units [4g, 4g+4) -> 16 z-columns
// (4 gates x 4 units). Wr slice in SMEM; c-state in registers of warp 0.
__global__ void __launch_bounds__(256) lstm_kernel(
    const float* __restrict__ Wr, float* __restrict__ dout)
{
    __shared__ float s[12288];            // 48 KB exactly
    float* sWr = s;                       // [16 cols][512 k]  (c-major)
    float* sh = s + 8192;                 // [8 b][512 k]
    float* szred = sh;                    // alias; used after GEMV reads finish

    const int tid = threadIdx.x;
    const int hu0 = blockIdx.x << 2;
    const int lane = tid & 31, warp = tid >> 5;
    const int cb = warp & 3, bb = warp >> 2;  // col-block (=gate), batch-block
    const int gb = tid >> 2, gu = tid & 3;    // gate-thread mapping (tid<32)

    // load Wr slice once:  sWr[c*512+k] = Wr[k][512*gate + hu0 + u]
    for (int idx = tid; idx < 8192; idx += 256) {
        int c = idx >> 9, k = idx & 511;
        int col = ((c >> 2) << 9) + hu0 + (c & 3);
        sWr[idx] = Wr[k * 2048 + col];
    }

    float creg = 0.f;
    if (tid < 32) g_hbuf[0][gb * 512 + hu0 + gu] = 0.f;   // h0 = 0
    if (tid < 32) __threadfence();
    grid_barrier(NBLK_LSTM);

    for (int t = 0; t < TD; t++) {
        const int cur = t & 1, nxt = cur ^ 1;

        // prefetch Xg (consumed ~2k cycles later)
        float xg0 = 0.f, xg1 = 0.f, xg2 = 0.f, xg3 = 0.f;
        if (tid < 32) {
            const float* xr = &g_Xg[((gb << 8) + t) * 2048 + hu0 + gu];
            xg0 = xr[0]; xg1 = xr[512]; xg2 = xr[1024]; xg3 = xr[1536];
        }

        // stage h into SMEM
        const float4* src = (const float4*)g_hbuf[cur];
        float4* dst = (float4*)sh;
#pragma unroll
        for (int i = 0; i < 4; i++) dst[tid + (i << 8)] = src[tid + (i << 8)];
        __syncthreads();

        // GEMV: warp (cb,bb) computes z[bb*4..+3][cb*4..+3] over k (lane-interleaved)
        float acc[4][4];
#pragma unroll
        for (int i = 0; i < 4; i++)
#pragma unroll
            for (int j = 0; j < 4; j++) acc[i][j] = 0.f;

#pragma unroll
        for (int kk = 0; kk < 16; kk++) {
            int k = (kk << 5) | lane;
            float h0 = sh[((bb << 2) + 0) * 512 + k];
            float h1 = sh[((bb << 2) + 1) * 512 + k];
            float h2 = sh[((bb << 2) + 2) * 512 + k];
            float h3 = sh[((bb << 2) + 3) * 512 + k];
            float w0 = sWr[((cb << 2) + 0) * 512 + k];
            float w1 = sWr[((cb << 2) + 1) * 512 + k];
            float w2 = sWr[((cb << 2) + 2) * 512 + k];
            float w3 = sWr[((cb << 2) + 3) * 512 + k];
            acc[0][0] += h0 * w0; acc[0][1] += h0 * w1; acc[0][2] += h0 * w2; acc[0][3] += h0 * w3;
            acc[1][0] += h1 * w0; acc[1][1] += h1 * w1; acc[1][2] += h1 * w2; acc[1][3] += h1 * w3;
            acc[2][0] += h2 * w0; acc[2][1] += h2 * w1; acc[2][2] += h2 * w2; acc[2][3] += h2 * w3;
            acc[3][0] += h3 * w0; acc[3][1] += h3 * w1; acc[3][2] += h3 * w2; acc[3][3] += h3 * w3;
        }

        // butterfly reduce over 32 k-lanes
#pragma unroll
        for (int off = 16; off; off >>= 1)
#pragma unroll
            for (int i = 0; i < 4; i++)
#pragma unroll
                for (int j = 0; j < 4; j++)
                    acc[i][j] += __shfl_xor_sync(0xffffffffu, acc[i][j], off);

        __syncthreads();   // all sh reads done -> safe to alias szred
        if (lane < 16) {
            int i = lane >> 2, j = lane & 3;
            szred[((bb << 2) + i) * 16 + ((cb << 2) + j)] = acc[i][j];
        }
        __syncthreads();

        if (tid < 32) {
            float zi = szred[gb * 16 + 0 + gu] + xg0;
            float zf = szred[gb * 16 + 4 + gu] + xg1;
            float zg = szred[gb * 16 + 8 + gu] + xg2;
            float zo = szred[gb * 16 + 12 + gu] + xg3;
            float ig = 1.f / (1.f + __expf(-zi));
            float fg = 1.f / (1.f + __expf(-zf));
            float gg = tanhf(zg);
            float og = 1.f / (1.f + __expf(-zo));
            creg = fg * creg + ig * gg;
            float h = og * tanhf(creg);
            g_hbuf[nxt][gb * 512 + hu0 + gu] = h;
            g_XC[((gb << 8) + t) * 1024 + hu0 + gu] = h;   // x sequence
            if (t == TD - 1) {
                dout[ROWS * MEL + gb * 512 + hu0 + gu] = h;                 // state_h
                dout[ROWS * MEL + BATCH * D + gb * 512 + hu0 + gu] = creg;  // state_c
            }
            __threadfence();
        }
        grid_barrier(NBLK_LSTM);
    }
}

// ----------------------------- attention scores -----------------------------
// scores[b][t][e] = sum_d tanh(h1[b][e][d] + h2[b][t][d]) * W3[d]
// tile: 16 t x 64 e per CTA, d staged in 64-chunks. MUFU-bound by design.
__global__ void __launch_bounds__(256) scores_kernel(const float* __restrict__ W3)
{
    __shared__ float sh1[64 * 65];   // [d][e] transposed, padded
    __shared__ float sh2[16 * 64];   // [t][d]
    __shared__ float sW3[512];

    const int tid = threadIdx.x;
    const int b = blockIdx.z, t0 = blockIdx.y << 4, e0 = blockIdx.x << 6;
    const int e = tid & 63, tg = tid >> 6;

    sW3[tid] = W3[tid];
    sW3[tid + 256] = W3[tid + 256];

    float acc[4] = {0.f, 0.f, 0.f, 0.f};

    for (int dc = 0; dc < 512; dc += 64) {
        __syncthreads();
        // load h1 tile transposed
#pragma unroll
        for (int i = 0; i < 4; i++) {
            int q = tid + (i << 8);
            int er = q >> 4, d4 = (q & 15) << 2;
            float4 v = *(const float4*)&g_h1[(long)(b * 256 + e0 + er) * 512 + dc + d4];
            sh1[(d4 + 0) * 65 + er] = v.x;
            sh1[(d4 + 1) * 65 + er] = v.y;
            sh1[(d4 + 2) * 65 + er] = v.z;
            sh1[(d4 + 3) * 65 + er] = v.w;
        }
        // load h2 tile
        {
            int tt = tid >> 4, d4 = (tid & 15) << 2;
            float4 v = *(const float4*)&g_h2[(long)(b * 256 + t0 + tt) * 512 + dc + d4];
            *(float4*)&sh2[tt * 64 + d4] = v;
        }
        __syncthreads();

#pragma unroll 8
        for (int d = 0; d < 64; d++) {
            float h1v = sh1[d * 65 + e];
            float w = sW3[dc + d];
#pragma unroll
            for (int i = 0; i < 4; i++) {
                float v = h1v + sh2[(tg * 4 + i) * 64 + d];
                acc[i] += fast_tanh(v) * w;
            }
        }
    }

#pragma unroll
    for (int i = 0; i < 4; i++)
        g_scores[(long)(b * 256 + t0 + tg * 4 + i) * 256 + e0 + e] = acc[i];
}

// ----------------------------- row softmax (in place) -----------------------
__global__ void __launch_bounds__(256) softmax_kernel()
{
    float* p = g_scores + (long)blockIdx.x * 256;
    const int tid = threadIdx.x;
    const int lane = tid & 31, w = tid >> 5;
    __shared__ float redm[8];
    __shared__ float reds[8];

    float v = p[tid];
    float m = v;
#pragma unroll
    for (int o = 16; o; o >>= 1) m = fmaxf(m, __shfl_xor_sync(0xffffffffu, m, o));
    if (lane == 0) redm[w] = m;
    __syncthreads();
    if (tid < 32) {
        float x = (tid < 8) ? redm[tid] : -1e30f;
#pragma unroll
        for (int o = 4; o; o >>= 1) x = fmaxf(x, __shfl_xor_sync(0xffffffffu, x, o));
        if (tid == 0) redm[0] = x;
    }
    __syncthreads();
    float ev = __expf(v - redm[0]);
    float ssum = ev;
#pragma unroll
    for (int o = 16; o; o >>= 1) ssum += __shfl_xor_sync(0xffffffffu, ssum, o);
    if (lane == 0) reds[w] = ssum;
    __syncthreads();
    if (tid < 32) {
        float x = (tid < 8) ? reds[tid] : 0.f;
#pragma unroll
        for (int o = 4; o; o >>= 1) x += __shfl_xor_sync(0xffffffffu, x, o);
        if (tid == 0) reds[0] = x;
    }
    __syncthreads();
    p[tid] = ev / reds[0];
}

// ----------------------------- launch ---------------------------------------
extern "C" void kernel_launch(void* const* d_in, const int* in_sizes, int n_in,
                              void* d_out, int out_size)
{
    const float* inputs   = (const float*)d_in[0];
    const float* attended = (const float*)d_in[1];
    const float* Wk       = (const float*)d_in[2];
    const float* Wr       = (const float*)d_in[3];
    const float* lstm_b   = (const float*)d_in[4];
    const float* W1       = (const float*)d_in[5];
    const float* b1       = (const float*)d_in[6];
    const float* W3       = (const float*)d_in[7];
    /* b3 (d_in[8]) cancels in softmax */
    const float* Wout     = (const float*)d_in[9];
    const float* bout     = (const float*)d_in[10];
    float* dout = (float*)d_out;

    static float* pXg = nullptr;
    static float* pH1 = nullptr;
    static float* pH2 = nullptr;
    static float* pXC = nullptr;
    static float* pSc = nullptr;
    if (!pXg) {
        cudaGetSymbolAddress((void**)&pXg, g_Xg);
        cudaGetSymbolAddress((void**)&pH1, g_h1);
        cudaGetSymbolAddress((void**)&pH2, g_h2);
        cudaGetSymbolAddress((void**)&pXC, g_XC);
        cudaGetSymbolAddress((void**)&pSc, g_scores);
    }

    // 1. Xg = inputs @ Wk + lstm_b              [2048,2048] K=80
    sgemm_kernel<<<dim3(32, 32, 1), 256>>>(inputs, DIN, 0, Wk, 4 * D, 0,
                                           pXg, 4 * D, 0, ROWS, 4 * D, DIN, lstm_b);
    // 2. h1 = attended @ W1 + b1                [2048,512] K=512 (independent of LSTM)
    sgemm_kernel<<<dim3(8, 32, 1), 256>>>(attended, D, 0, W1, D, 0,
                                          pH1, D, 0, ROWS, D, D, b1);
    // 3. LSTM (persistent, writes x into g_XC[:, :512] and states into dout)
    lstm_kernel<<<NBLK_LSTM, 256>>>(Wr, dout);
    // 4. h2 = x @ W1 + b1                       [2048,512] K=512
    sgemm_kernel<<<dim3(8, 32, 1), 256>>>(pXC, 2 * D, 0, W1, D, 0,
                                          pH2, D, 0, ROWS, D, D, b1);
    // 5. scores
    scores_kernel<<<dim3(4, 16, 8), 256>>>(W3);
    // 6. softmax (in place -> attn)
    softmax_kernel<<<ROWS, 256>>>();
    // 7. weighted = attn @ attended  (batched)  -> g_XC[:, 512:]
    sgemm_kernel<<<dim3(8, 4, 8), 256>>>(pSc, TE, (long)TD * TE,
                                         attended, D, (long)TE * D,
                                         pXC + D, 2 * D, (long)TD * 2 * D,
                                         TD, D, TE, nullptr);
    // 8. out = [x | weighted] @ Wout + bout     [2048,80] K=1024
    sgemm_kernel<<<dim3(2, 32, 1), 256>>>(pXC, 2 * D, 0, Wout, MEL, 0,
                                          dout, MEL, 0, ROWS, MEL, 2 * D, bout);
}

// round 3
// speedup vs baseline: 1.1159x; 1.1159x over previous
#include <cuda_runtime.h>
#include <math.h>

#define BATCH 8
#define TD 256
#define TE 256
#define DIN 80
#define D 512
#define MEL 80
#define ROWS (BATCH*TD)          // 2048
#define NBLK_LSTM 128

// ----------------------------- scratch (device globals) ---------------------
__device__ __align__(16) float g_Xg[ROWS * 4 * D];        // inputs@Wk + b : [2048][2048]
__device__ __align__(16) float g_h1[ROWS * D];            // attended@W1+b1: [2048][512]
__device__ __align__(16) float g_h2[ROWS * D];            // x@W1+b1      : [2048][512]
__device__ __align__(16) float g_XC[ROWS * 2 * D];        // [x | weighted]: [2048][1024]
__device__ __align__(16) float g_scores[BATCH * TD * TE]; // scores/attn   : [2048][256]
__device__ __align__(16) float g_hbuf[2][BATCH * D];      // double-buffered h
__device__ unsigned g_count;   // barrier arrivals (reset by winner)
__device__ unsigned g_gen;     // barrier generation (monotonic across replays)

// ----------------------------- helpers --------------------------------------
__device__ __forceinline__ float fast_tanh(float x) {
    float y;
    asm("tanh.approx.f32 %0, %1;" : "=f"(y) : "f"(x));
    return y;
}

// release/acquire grid barrier: no membar.gl, no sleep.
__device__ __forceinline__ void grid_barrier(unsigned& my_gen) {
    __syncthreads();
    if (threadIdx.x == 0) {
        unsigned old;
        asm volatile("atom.acq_rel.gpu.global.add.u32 %0, [%1], %2;"
                     : "=r"(old) : "l"(&g_count), "r"(1u) : "memory");
        if (old == NBLK_LSTM - 1) {
            asm volatile("st.relaxed.gpu.global.u32 [%0], %1;"
                         :: "l"(&g_count), "r"(0u) : "memory");
            asm volatile("st.release.gpu.global.u32 [%0], %1;"
                         :: "l"(&g_gen), "r"(my_gen + 1u) : "memory");
        } else {
            unsigned v;
            do {
                asm volatile("ld.acquire.gpu.global.u32 %0, [%1];"
                             : "=r"(v) : "l"(&g_gen) : "memory");
            } while (v == my_gen);
        }
    }
    my_gen++;
    __syncthreads();
}

// ----------------------------- fast SGEMM: 128x64 tile, 8x4 micro -----------
// C[M,N] = A[M,K] @ B[K,N] (+ bias). Requires M%128==0, K%16==0; N guarded.
__global__ void __launch_bounds__(256) sgemm128(
    const float* __restrict__ A, int lda, long sA,
    const float* __restrict__ B, int ldb, long sB,
    float* __restrict__ C, int ldc, long sC,
    int M, int N, int K, const float* __restrict__ bias)
{
    __shared__ float As[16][132];   // [k][m] transposed, padded
    __shared__ float Bs[16][64];    // [k][n]

    const int tid = threadIdx.x;
    const int tx = tid & 15;        // 16 groups of 4 cols
    const int ty = tid >> 4;        // 16 groups of 8 rows
    const int m0 = blockIdx.y << 7, n0 = blockIdx.x << 6;
    A += (long)blockIdx.z * sA;
    B += (long)blockIdx.z * sB;
    C += (long)blockIdx.z * sC;

    const int ar = tid >> 2, ac4 = (tid & 3) << 2;   // A: 64 rows x 4 k per pass, 2 passes
    const int br = tid >> 4, bc4 = (tid & 15) << 2;  // B: 16 k x 64 n

    float acc[8][4];
#pragma unroll
    for (int i = 0; i < 8; i++)
#pragma unroll
        for (int j = 0; j < 4; j++) acc[i][j] = 0.f;

    for (int k0 = 0; k0 < K; k0 += 16) {
        // stage A transposed: As[k][m]
#pragma unroll
        for (int h = 0; h < 2; h++) {
            int m = ar + (h << 6);
            float4 v = *(const float4*)&A[(long)(m0 + m) * lda + k0 + ac4];
            As[ac4 + 0][m] = v.x;
            As[ac4 + 1][m] = v.y;
            As[ac4 + 2][m] = v.z;
            As[ac4 + 3][m] = v.w;
        }
        // stage B
        float4 bv = make_float4(0.f, 0.f, 0.f, 0.f);
        if (n0 + bc4 + 3 < N) {
            bv = *(const float4*)&B[(long)(k0 + br) * ldb + n0 + bc4];
        } else {
            float* p = (float*)&bv;
#pragma unroll
            for (int c = 0; c < 4; c++)
                if (n0 + bc4 + c < N) p[c] = B[(long)(k0 + br) * ldb + n0 + bc4 + c];
        }
        *(float4*)&Bs[br][bc4] = bv;
        __syncthreads();

#pragma unroll
        for (int k = 0; k < 16; k++) {
            float4 a0 = *(const float4*)&As[k][ty * 8];
            float4 a1 = *(const float4*)&As[k][ty * 8 + 4];
            float4 b4 = *(const float4*)&Bs[k][tx * 4];
            acc[0][0] += a0.x * b4.x; acc[0][1] += a0.x * b4.y; acc[0][2] += a0.x * b4.z; acc[0][3] += a0.x * b4.w;
            acc[1][0] += a0.y * b4.x; acc[1][1] += a0.y * b4.y; acc[1][2] += a0.y * b4.z; acc[1][3] += a0.y * b4.w;
            acc[2][0] += a0.z * b4.x; acc[2][1] += a0.z * b4.y; acc[2][2] += a0.z * b4.z; acc[2][3] += a0.z * b4.w;
            acc[3][0] += a0.w * b4.x; acc[3][1] += a0.w * b4.y; acc[3][2] += a0.w * b4.z; acc[3][3] += a0.w * b4.w;
            acc[4][0] += a1.x * b4.x; acc[4][1] += a1.x * b4.y; acc[4][2] += a1.x * b4.z; acc[4][3] += a1.x * b4.w;
            acc[5][0] += a1.y * b4.x; acc[5][1] += a1.y * b4.y; acc[5][2] += a1.y * b4.z; acc[5][3] += a1.y * b4.w;
            acc[6][0] += a1.z * b4.x; acc[6][1] += a1.z * b4.y; acc[6][2] += a1.z * b4.z; acc[6][3] += a1.z * b4.w;
            acc[7][0] += a1.w * b4.x; acc[7][1] += a1.w * b4.y; acc[7][2] += a1.w * b4.z; acc[7][3] += a1.w * b4.w;
        }
        __syncthreads();
    }

#pragma unroll
    for (int i = 0; i < 8; i++) {
        int m = m0 + ty * 8 + i;
#pragma unroll
        for (int j = 0; j < 4; j++) {
            int n = n0 + tx * 4 + j;
            if (n < N) {
                float v = acc[i][j];
                if (bias) v += bias[n];
                C[(long)m * ldc + n] = v;
            }
        }
    }
}

// ----------------------------- persistent LSTM ------------------------------
// 128 CTAs x 256 threads. CTA g owns hidden units [4g, 4g+4) -> 16 z-columns
// (4 gates x 4 units). Wr slice in SMEM; c-state in registers of warp 0.
__global__ void __launch_bounds__(256) lstm_kernel(
    const float* __restrict__ Wr, float* __restrict__ dout)
{
    __shared__ float s[12288];            // 48 KB exactly
    float* sWr = s;                       // [16 cols][512 k]  (c-major)
    float* sh = s + 8192;                 // [8 b][512 k]
    float* szred = sh;                    // alias; used after GEMV reads finish
    float4* sWrv = (float4*)sWr;
    float4* shv = (float4*)sh;

    const int tid = threadIdx.x;
    const int hu0 = blockIdx.x << 2;
    const int lane = tid & 31, warp = tid >> 5;
    const int cb = warp & 3, bb = warp >> 2;  // col-block (=gate), batch-block
    const int gb = tid >> 2, gu = tid & 3;    // gate-thread mapping (tid<32)

    // load Wr slice once:  sWr[c*512+k] = Wr[k][512*gate + hu0 + u]
    for (int idx = tid; idx < 8192; idx += 256) {
        int c = idx >> 9, k = idx & 511;
        int col = ((c >> 2) << 9) + hu0 + (c & 3);
        sWr[idx] = Wr[k * 2048 + col];
    }

    unsigned my_gen;
    if (tid == 0) {
        asm volatile("ld.acquire.gpu.global.u32 %0, [%1];"
                     : "=r"(my_gen) : "l"(&g_gen) : "memory");
    }

    float creg = 0.f;
    if (tid < 32) g_hbuf[0][gb * 512 + hu0 + gu] = 0.f;   // h0 = 0
    grid_barrier(my_gen);

    for (int t = 0; t < TD; t++) {
        const int cur = t & 1, nxt = cur ^ 1;

        // prefetch Xg (consumed ~2k cycles later)
        float xg0 = 0.f, xg1 = 0.f, xg2 = 0.f, xg3 = 0.f;
        if (tid < 32) {
            const float* xr = &g_Xg[((gb << 8) + t) * 2048 + hu0 + gu];
            xg0 = xr[0]; xg1 = xr[512]; xg2 = xr[1024]; xg3 = xr[1536];
        }

        // stage h into SMEM (16 KB)
        const float4* src = (const float4*)g_hbuf[cur];
        float4* dst = (float4*)sh;
#pragma unroll
        for (int i = 0; i < 4; i++) dst[tid + (i << 8)] = src[tid + (i << 8)];
        __syncthreads();

        // GEMV: warp (cb,bb) computes z[bb*4..+3][cb*4..+3], k lane-vectorized
        float acc[4][4];
#pragma unroll
        for (int i = 0; i < 4; i++)
#pragma unroll
            for (int j = 0; j < 4; j++) acc[i][j] = 0.f;

#pragma unroll
        for (int kk = 0; kk < 4; kk++) {
            const int kv = (kk << 5) + lane;
            float4 h0 = shv[((bb << 2) + 0) * 128 + kv];
            float4 h1 = shv[((bb << 2) + 1) * 128 + kv];
            float4 h2 = shv[((bb << 2) + 2) * 128 + kv];
            float4 h3 = shv[((bb << 2) + 3) * 128 + kv];
            float4 w0 = sWrv[((cb << 2) + 0) * 128 + kv];
            float4 w1 = sWrv[((cb << 2) + 1) * 128 + kv];
            float4 w2 = sWrv[((cb << 2) + 2) * 128 + kv];
            float4 w3 = sWrv[((cb << 2) + 3) * 128 + kv];
#define DOT4(a,b) ((a).x*(b).x + (a).y*(b).y + (a).z*(b).z + (a).w*(b).w)
            acc[0][0] += DOT4(h0, w0); acc[0][1] += DOT4(h0, w1); acc[0][2] += DOT4(h0, w2); acc[0][3] += DOT4(h0, w3);
            acc[1][0] += DOT4(h1, w0); acc[1][1] += DOT4(h1, w1); acc[1][2] += DOT4(h1, w2); acc[1][3] += DOT4(h1, w3);
            acc[2][0] += DOT4(h2, w0); acc[2][1] += DOT4(h2, w1); acc[2][2] += DOT4(h2, w2); acc[2][3] += DOT4(h2, w3);
            acc[3][0] += DOT4(h3, w0); acc[3][1] += DOT4(h3, w1); acc[3][2] += DOT4(h3, w2); acc[3][3] += DOT4(h3, w3);
#undef DOT4
        }

        // butterfly reduce over 32 k-lanes
#pragma unroll
        for (int off = 16; off; off >>= 1)
#pragma unroll
            for (int i = 0; i < 4; i++)
#pragma unroll
                for (int j = 0; j < 4; j++)
                    acc[i][j] += __shfl_xor_sync(0xffffffffu, acc[i][j], off);

        __syncthreads();   // all sh reads done -> safe to alias szred
        if (lane < 16) {
            int i = lane >> 2, j = lane & 3;
            szred[((bb << 2) + i) * 16 + ((cb << 2) + j)] = acc[i][j];
        }
        __syncthreads();

        if (tid < 32) {
            float zi = szred[gb * 16 + 0 + gu] + xg0;
            float zf = szred[gb * 16 + 4 + gu] + xg1;
            float zg = szred[gb * 16 + 8 + gu] + xg2;
            float zo = szred[gb * 16 + 12 + gu] + xg3;
            float ig = 1.f / (1.f + __expf(-zi));
            float fg = 1.f / (1.f + __expf(-zf));
            float gg = tanhf(zg);
            float og = 1.f / (1.f + __expf(-zo));
            creg = fg * creg + ig * gg;
            float h = og * tanhf(creg);
            g_hbuf[nxt][gb * 512 + hu0 + gu] = h;
            g_XC[((gb << 8) + t) * 1024 + hu0 + gu] = h;   // x sequence
            if (t == TD - 1) {
                dout[ROWS * MEL + gb * 512 + hu0 + gu] = h;                 // state_h
                dout[ROWS * MEL + BATCH * D + gb * 512 + hu0 + gu] = creg;  // state_c
            }
        }
        if (t < TD - 1) grid_barrier(my_gen);   // release publishes h writes
    }
}

// ----------------------------- attention scores -----------------------------
// scores[b][t][e] = sum_d tanh(h1[b][e][d] + h2[b][t][d]) * W3[d]
// tile: 16 t x 64 e per CTA, d staged in 64-chunks. MUFU-bound by design.
__global__ void __launch_bounds__(256) scores_kernel(const float* __restrict__ W3)
{
    __shared__ float sh1[64 * 65];   // [d][e] transposed, padded
    __shared__ float sh2[16 * 64];   // [t][d]
    __shared__ float sW3[512];

    const int tid = threadIdx.x;
    const int b = blockIdx.z, t0 = blockIdx.y << 4, e0 = blockIdx.x << 6;
    const int e = tid & 63, tg = tid >> 6;

    sW3[tid] = W3[tid];
    sW3[tid + 256] = W3[tid + 256];

    float acc[4] = {0.f, 0.f, 0.f, 0.f};

    for (int dc = 0; dc < 512; dc += 64) {
        __syncthreads();
        // load h1 tile transposed
#pragma unroll
        for (int i = 0; i < 4; i++) {
            int q = tid + (i << 8);
            int er = q >> 4, d4 = (q & 15) << 2;
            float4 v = *(const float4*)&g_h1[(long)(b * 256 + e0 + er) * 512 + dc + d4];
            sh1[(d4 + 0) * 65 + er] = v.x;
            sh1[(d4 + 1) * 65 + er] = v.y;
            sh1[(d4 + 2) * 65 + er] = v.z;
            sh1[(d4 + 3) * 65 + er] = v.w;
        }
        // load h2 tile
        {
            int tt = tid >> 4, d4 = (tid & 15) << 2;
            float4 v = *(const float4*)&g_h2[(long)(b * 256 + t0 + tt) * 512 + dc + d4];
            *(float4*)&sh2[tt * 64 + d4] = v;
        }
        __syncthreads();

#pragma unroll 8
        for (int d = 0; d < 64; d++) {
            float h1v = sh1[d * 65 + e];
            float w = sW3[dc + d];
#pragma unroll
            for (int i = 0; i < 4; i++) {
                float v = h1v + sh2[(tg * 4 + i) * 64 + d];
                acc[i] += fast_tanh(v) * w;
            }
        }
    }

#pragma unroll
    for (int i = 0; i < 4; i++)
        g_scores[(long)(b * 256 + t0 + tg * 4 + i) * 256 + e0 + e] = acc[i];
}

// ----------------------------- row softmax (in place) -----------------------
__global__ void __launch_bounds__(256) softmax_kernel()
{
    float* p = g_scores + (long)blockIdx.x * 256;
    const int tid = threadIdx.x;
    const int lane = tid & 31, w = tid >> 5;
    __shared__ float redm[8];
    __shared__ float reds[8];

    float v = p[tid];
    float m = v;
#pragma unroll
    for (int o = 16; o; o >>= 1) m = fmaxf(m, __shfl_xor_sync(0xffffffffu, m, o));
    if (lane == 0) redm[w] = m;
    __syncthreads();
    if (tid < 32) {
        float x = (tid < 8) ? redm[tid] : -1e30f;
#pragma unroll
        for (int o = 4; o; o >>= 1) x = fmaxf(x, __shfl_xor_sync(0xffffffffu, x, o));
        if (tid == 0) redm[0] = x;
    }
    __syncthreads();
    float ev = __expf(v - redm[0]);
    float ssum = ev;
#pragma unroll
    for (int o = 16; o; o >>= 1) ssum += __shfl_xor_sync(0xffffffffu, ssum, o);
    if (lane == 0) reds[w] = ssum;
    __syncthreads();
    if (tid < 32) {
        float x = (tid < 8) ? reds[tid] : 0.f;
#pragma unroll
        for (int o = 4; o; o >>= 1) x += __shfl_xor_sync(0xffffffffu, x, o);
        if (tid == 0) reds[0] = x;
    }
    __syncthreads();
    p[tid] = ev / reds[0];
}

// ----------------------------- launch ---------------------------------------
extern "C" void kernel_launch(void* const* d_in, const int* in_sizes, int n_in,
                              void* d_out, int out_size)
{
    const float* inputs   = (const float*)d_in[0];
    const float* attended = (const float*)d_in[1];
    const float* Wk       = (const float*)d_in[2];
    const float* Wr       = (const float*)d_in[3];
    const float* lstm_b   = (const float*)d_in[4];
    const float* W1       = (const float*)d_in[5];
    const float* b1       = (const float*)d_in[6];
    const float* W3       = (const float*)d_in[7];
    /* b3 (d_in[8]) cancels in softmax */
    const float* Wout     = (const float*)d_in[9];
    const float* bout     = (const float*)d_in[10];
    float* dout = (float*)d_out;

    static float* pXg = nullptr;
    static float* pH1 = nullptr;
    static float* pH2 = nullptr;
    static float* pXC = nullptr;
    static float* pSc = nullptr;
    if (!pXg) {
        cudaGetSymbolAddress((void**)&pXg, g_Xg);
        cudaGetSymbolAddress((void**)&pH1, g_h1);
        cudaGetSymbolAddress((void**)&pH2, g_h2);
        cudaGetSymbolAddress((void**)&pXC, g_XC);
        cudaGetSymbolAddress((void**)&pSc, g_scores);
    }

    // 1. Xg = inputs @ Wk + lstm_b              [2048,2048] K=80
    sgemm128<<<dim3(32, 16, 1), 256>>>(inputs, DIN, 0, Wk, 4 * D, 0,
                                       pXg, 4 * D, 0, ROWS, 4 * D, DIN, lstm_b);
    // 2. h1 = attended @ W1 + b1                [2048,512] K=512
    sgemm128<<<dim3(8, 16, 1), 256>>>(attended, D, 0, W1, D, 0,
                                      pH1, D, 0, ROWS, D, D, b1);
    // 3. LSTM (persistent, writes x into g_XC[:, :512] and states into dout)
    lstm_kernel<<<NBLK_LSTM, 256>>>(Wr, dout);
    // 4. h2 = x @ W1 + b1                       [2048,512] K=512
    sgemm128<<<dim3(8, 16, 1), 256>>>(pXC, 2 * D, 0, W1, D, 0,
                                      pH2, D, 0, ROWS, D, D, b1);
    // 5. scores
    scores_kernel<<<dim3(4, 16, 8), 256>>>(W3);
    // 6. softmax (in place -> attn)
    softmax_kernel<<<ROWS, 256>>>();
    // 7. weighted = attn @ attended  (batched)  -> g_XC[:, 512:]
    sgemm128<<<dim3(8, 2, 8), 256>>>(pSc, TE, (long)TD * TE,
                                     attended, D, (long)TE * D,
                                     pXC + D, 2 * D, (long)TD * 2 * D,
                                     TD, D, TE, nullptr);
    // 8. out = [x | weighted] @ Wout + bout     [2048,80] K=1024
    sgemm128<<<dim3(2, 16, 1), 256>>>(pXC, 2 * D, 0, Wout, MEL, 0,
                                      dout, MEL, 0, ROWS, MEL, 2 * D, bout);
}

// round 4
// speedup vs baseline: 1.1543x; 1.0345x over previous
#include <cuda_runtime.h>
#include <math.h>

#define BATCH 8
#define TD 256
#define TE 256
#define DIN 80
#define D 512
#define MEL 80
#define ROWS (BATCH*TD)          // 2048
#define NBLK_LSTM 128

// ----------------------------- scratch (device globals) ---------------------
__device__ __align__(16) float g_Xg[ROWS * 4 * D];        // inputs@Wk + b : [2048][2048]
__device__ __align__(16) float g_h1[ROWS * D];            // attended@W1+b1: [2048][512]
__device__ __align__(16) float g_h2[ROWS * D];            // x@W1+b1      : [2048][512]
__device__ __align__(16) float g_XC[ROWS * 2 * D];        // [x | weighted]: [2048][1024]
__device__ __align__(16) float g_scores[BATCH * TD * TE]; // scores/attn   : [2048][256]
__device__ __align__(16) float g_part[4 * ROWS * D];      // split-K partials
__device__ __align__(16) float g_hbuf[2][BATCH * D];      // double-buffered h
__device__ unsigned g_flags[NBLK_LSTM * 8];               // 32B-padded per-CTA flags (zero-init)

// ----------------------------- helpers --------------------------------------
__device__ __forceinline__ float fast_tanh(float x) {
    float y;
    asm("tanh.approx.f32 %0, %1;" : "=f"(y) : "f"(x));
    return y;
}
__device__ __forceinline__ unsigned ldg_relaxed_u32(const unsigned* p) {
    unsigned v;
    asm volatile("ld.relaxed.gpu.global.u32 %0, [%1];" : "=r"(v) : "l"(p) : "memory");
    return v;
}
__device__ __forceinline__ void stg_relaxed_u32(unsigned* p, unsigned v) {
    asm volatile("st.relaxed.gpu.global.u32 [%0], %1;" :: "l"(p), "r"(v) : "memory");
}
__device__ __forceinline__ void stg_relaxed_f32(float* p, float v) {
    asm volatile("st.relaxed.gpu.global.f32 [%0], %1;" :: "l"(p), "f"(v) : "memory");
}
__device__ __forceinline__ float4 ldg_relaxed_f4(const float4* p) {
    float4 v;
    asm volatile("ld.relaxed.gpu.global.v4.f32 {%0,%1,%2,%3}, [%4];"
                 : "=f"(v.x), "=f"(v.y), "=f"(v.z), "=f"(v.w) : "l"(p) : "memory");
    return v;
}
__device__ __forceinline__ void fence_gpu() {
    asm volatile("fence.acq_rel.gpu;" ::: "memory");
}

// ----------------------------- fast SGEMM: 128x64 tile, 8x4 micro -----------
// C[M,N] = A[M,K] @ B[K,N] (+ bias). Requires M%128==0, K%16==0; N guarded.
// blockIdx.z selects a (sA, sB, sC) offset slice (batch OR split-K).
__global__ void __launch_bounds__(256) sgemm128(
    const float* __restrict__ A, int lda, long sA,
    const float* __restrict__ B, int ldb, long sB,
    float* __restrict__ C, int ldc, long sC,
    int M, int N, int K, const float* __restrict__ bias)
{
    __shared__ float As[16][132];   // [k][m] transposed, padded
    __shared__ float Bs[16][64];    // [k][n]

    const int tid = threadIdx.x;
    const int tx = tid & 15;
    const int ty = tid >> 4;
    const int m0 = blockIdx.y << 7, n0 = blockIdx.x << 6;
    A += (long)blockIdx.z * sA;
    B += (long)blockIdx.z * sB;
    C += (long)blockIdx.z * sC;

    const int ar = tid >> 2, ac4 = (tid & 3) << 2;
    const int br = tid >> 4, bc4 = (tid & 15) << 2;

    float acc[8][4];
#pragma unroll
    for (int i = 0; i < 8; i++)
#pragma unroll
        for (int j = 0; j < 4; j++) acc[i][j] = 0.f;

    for (int k0 = 0; k0 < K; k0 += 16) {
#pragma unroll
        for (int h = 0; h < 2; h++) {
            int m = ar + (h << 6);
            float4 v = *(const float4*)&A[(long)(m0 + m) * lda + k0 + ac4];
            As[ac4 + 0][m] = v.x;
            As[ac4 + 1][m] = v.y;
            As[ac4 + 2][m] = v.z;
            As[ac4 + 3][m] = v.w;
        }
        float4 bv = make_float4(0.f, 0.f, 0.f, 0.f);
        if (n0 + bc4 + 3 < N) {
            bv = *(const float4*)&B[(long)(k0 + br) * ldb + n0 + bc4];
        } else {
            float* p = (float*)&bv;
#pragma unroll
            for (int c = 0; c < 4; c++)
                if (n0 + bc4 + c < N) p[c] = B[(long)(k0 + br) * ldb + n0 + bc4 + c];
        }
        *(float4*)&Bs[br][bc4] = bv;
        __syncthreads();

#pragma unroll
        for (int k = 0; k < 16; k++) {
            float4 a0 = *(const float4*)&As[k][ty * 8];
            float4 a1 = *(const float4*)&As[k][ty * 8 + 4];
            float4 b4 = *(const float4*)&Bs[k][tx * 4];
            acc[0][0] += a0.x * b4.x; acc[0][1] += a0.x * b4.y; acc[0][2] += a0.x * b4.z; acc[0][3] += a0.x * b4.w;
            acc[1][0] += a0.y * b4.x; acc[1][1] += a0.y * b4.y; acc[1][2] += a0.y * b4.z; acc[1][3] += a0.y * b4.w;
            acc[2][0] += a0.z * b4.x; acc[2][1] += a0.z * b4.y; acc[2][2] += a0.z * b4.z; acc[2][3] += a0.z * b4.w;
            acc[3][0] += a0.w * b4.x; acc[3][1] += a0.w * b4.y; acc[3][2] += a0.w * b4.z; acc[3][3] += a0.w * b4.w;
            acc[4][0] += a1.x * b4.x; acc[4][1] += a1.x * b4.y; acc[4][2] += a1.x * b4.z; acc[4][3] += a1.x * b4.w;
            acc[5][0] += a1.y * b4.x; acc[5][1] += a1.y * b4.y; acc[5][2] += a1.y * b4.z; acc[5][3] += a1.y * b4.w;
            acc[6][0] += a1.z * b4.x; acc[6][1] += a1.z * b4.y; acc[6][2] += a1.z * b4.z; acc[6][3] += a1.z * b4.w;
            acc[7][0] += a1.w * b4.x; acc[7][1] += a1.w * b4.y; acc[7][2] += a1.w * b4.z; acc[7][3] += a1.w * b4.w;
        }
        __syncthreads();
    }

#pragma unroll
    for (int i = 0; i < 8; i++) {
        int m = m0 + ty * 8 + i;
#pragma unroll
        for (int j = 0; j < 4; j++) {
            int n = n0 + tx * 4 + j;
            if (n < N) {
                float v = acc[i][j];
                if (bias) v += bias[n];
                C[(long)m * ldc + n] = v;
            }
        }
    }
}

// ----------------------------- split-K partial reduce ------------------------
// out[i] = sum_p parts[p*pstride + i] + bias[i % bmod]; n % 4 == 0, bmod % 4 == 0
__global__ void __launch_bounds__(256) reduce_parts(
    const float* __restrict__ parts, long pstride, int nparts,
    const float* __restrict__ bias, int bmod, float* __restrict__ out, int n)
{
    int i = (blockIdx.x * 256 + threadIdx.x) << 2;
    if (i >= n) return;
    float4 a = *(const float4*)&parts[i];
    for (int p = 1; p < nparts; p++) {
        float4 b = *(const float4*)&parts[(long)p * pstride + i];
        a.x += b.x; a.y += b.y; a.z += b.z; a.w += b.w;
    }
    int bi = i % bmod;
    a.x += bias[bi]; a.y += bias[bi + 1]; a.z += bias[bi + 2]; a.w += bias[bi + 3];
    *(float4*)&out[i] = a;
}

// ----------------------------- persistent LSTM ------------------------------
// 128 CTAs x 256 threads; atomic-free all-poll-all flag barrier.
__global__ void __launch_bounds__(256) lstm_kernel(
    const float* __restrict__ Wr, float* __restrict__ dout)
{
    extern __shared__ float s[];
    float* sWr = s;                         // [16 cols][512 k]
    float* sh = s + 8192;                   // [8 b][512 k]
    float* szred = s + 8192 + 4096;         // [8 b][16 c]
    float4* sWrv = (float4*)sWr;
    float4* shv = (float4*)sh;
    __shared__ unsigned s_base;

    const int tid = threadIdx.x;
    const int hu0 = blockIdx.x << 2;
    const int lane = tid & 31, warp = tid >> 5;
    const int cb = warp & 3, bb = warp >> 2;  // col-block (=gate), batch-block
    const int gb = tid >> 2, gu = tid & 3;    // gate-thread mapping (tid<32)

    // load Wr slice once: sWr[c*512+k] = Wr[k][512*gate + hu0 + u]
    for (int idx = tid; idx < 8192; idx += 256) {
        int c = idx >> 9, k = idx & 511;
        int col = ((c >> 2) << 9) + hu0 + (c & 3);
        sWr[idx] = Wr[k * 2048 + col];
    }

    if (tid == 0) s_base = ldg_relaxed_u32(&g_flags[blockIdx.x * 8]);
    // h0 = 0 for the units this CTA owns
    if (tid < 32) stg_relaxed_f32(&g_hbuf[0][gb * 512 + hu0 + gu], 0.f);
    __syncthreads();
    const unsigned base = s_base;
    if (tid < 32) {
        fence_gpu();
        __syncwarp();
        if (tid == 0) stg_relaxed_u32(&g_flags[blockIdx.x * 8], base + 1);
    }

    float creg = 0.f;

    for (int t = 0; t < TD; t++) {
        const int cur = t & 1, nxt = cur ^ 1;
        const unsigned tgt = base + (unsigned)t + 1u;

        // prefetch Xg for this step (constant data; overlaps the poll)
        float xg0 = 0.f, xg1 = 0.f, xg2 = 0.f, xg3 = 0.f;
        if (tid < 32) {
            const float* xr = &g_Xg[((gb << 8) + t) * 2048 + hu0 + gu];
            xg0 = xr[0]; xg1 = xr[512]; xg2 = xr[1024]; xg3 = xr[1536];
        }

        // all-poll-all barrier: warp 0 watches all 128 flags
        if (warp == 0) {
            bool ok;
            do {
                unsigned f0 = ldg_relaxed_u32(&g_flags[(lane) * 8]);
                unsigned f1 = ldg_relaxed_u32(&g_flags[(lane + 32) * 8]);
                unsigned f2 = ldg_relaxed_u32(&g_flags[(lane + 64) * 8]);
                unsigned f3 = ldg_relaxed_u32(&g_flags[(lane + 96) * 8]);
                ok = ((int)(f0 - tgt) >= 0) & ((int)(f1 - tgt) >= 0) &
                     ((int)(f2 - tgt) >= 0) & ((int)(f3 - tgt) >= 0);
            } while (!__all_sync(0xffffffffu, ok));
            fence_gpu();
        }
        __syncthreads();

        // stage h into SMEM (16 KB), L2-coherent loads
        const float4* src = (const float4*)g_hbuf[cur];
#pragma unroll
        for (int i = 0; i < 4; i++) shv[tid + (i << 8)] = ldg_relaxed_f4(&src[tid + (i << 8)]);
        __syncthreads();

        // GEMV: warp (cb,bb) computes z[bb*4..+3][cb*4..+3], k lane-vectorized
        float acc[4][4];
#pragma unroll
        for (int i = 0; i < 4; i++)
#pragma unroll
            for (int j = 0; j < 4; j++) acc[i][j] = 0.f;

#pragma unroll
        for (int kk = 0; kk < 4; kk++) {
            const int kv = (kk << 5) + lane;
            float4 h0 = shv[((bb << 2) + 0) * 128 + kv];
            float4 h1 = shv[((bb << 2) + 1) * 128 + kv];
            float4 h2 = shv[((bb << 2) + 2) * 128 + kv];
            float4 h3 = shv[((bb << 2) + 3) * 128 + kv];
            float4 w0 = sWrv[((cb << 2) + 0) * 128 + kv];
            float4 w1 = sWrv[((cb << 2) + 1) * 128 + kv];
            float4 w2 = sWrv[((cb << 2) + 2) * 128 + kv];
            float4 w3 = sWrv[((cb << 2) + 3) * 128 + kv];
#define DOT4(a,b) ((a).x*(b).x + (a).y*(b).y + (a).z*(b).z + (a).w*(b).w)
            acc[0][0] += DOT4(h0, w0); acc[0][1] += DOT4(h0, w1); acc[0][2] += DOT4(h0, w2); acc[0][3] += DOT4(h0, w3);
            acc[1][0] += DOT4(h1, w0); acc[1][1] += DOT4(h1, w1); acc[1][2] += DOT4(h1, w2); acc[1][3] += DOT4(h1, w3);
            acc[2][0] += DOT4(h2, w0); acc[2][1] += DOT4(h2, w1); acc[2][2] += DOT4(h2, w2); acc[2][3] += DOT4(h2, w3);
            acc[3][0] += DOT4(h3, w0); acc[3][1] += DOT4(h3, w1); acc[3][2] += DOT4(h3, w2); acc[3][3] += DOT4(h3, w3);
#undef DOT4
        }

        // butterfly reduce over 32 k-lanes
#pragma unroll
        for (int off = 16; off; off >>= 1)
#pragma unroll
            for (int i = 0; i < 4; i++)
#pragma unroll
                for (int j = 0; j < 4; j++)
                    acc[i][j] += __shfl_xor_sync(0xffffffffu, acc[i][j], off);

        if (lane < 16) {
            int i = lane >> 2, j = lane & 3;
            szred[((bb << 2) + i) * 16 + ((cb << 2) + j)] = acc[i][j];
        }
        __syncthreads();

        if (tid < 32) {
            float zi = szred[gb * 16 + 0 + gu] + xg0;
            float zf = szred[gb * 16 + 4 + gu] + xg1;
            float zg = szred[gb * 16 + 8 + gu] + xg2;
            float zo = szred[gb * 16 + 12 + gu] + xg3;
            float ig = 1.f / (1.f + __expf(-zi));
            float fg = 1.f / (1.f + __expf(-zf));
            float gg = tanhf(zg);
            float og = 1.f / (1.f + __expf(-zo));
            creg = fg * creg + ig * gg;
            float h = og * tanhf(creg);
            stg_relaxed_f32(&g_hbuf[nxt][gb * 512 + hu0 + gu], h);
            g_XC[((gb << 8) + t) * 1024 + hu0 + gu] = h;   // x sequence
            if (t == TD - 1) {
                dout[ROWS * MEL + gb * 512 + hu0 + gu] = h;                 // state_h
                dout[ROWS * MEL + BATCH * D + gb * 512 + hu0 + gu] = creg;  // state_c
            }
            fence_gpu();
            __syncwarp();
            if (tid == 0) stg_relaxed_u32(&g_flags[blockIdx.x * 8], base + (unsigned)t + 2u);
        }
    }
}

// ----------------------------- attention scores -----------------------------
__global__ void __launch_bounds__(256) scores_kernel(const float* __restrict__ W3)
{
    __shared__ float sh1[64 * 65];   // [d][e] transposed, padded
    __shared__ float sh2[16 * 64];   // [t][d]
    __shared__ float sW3[512];

    const int tid = threadIdx.x;
    const int b = blockIdx.z, t0 = blockIdx.y << 4, e0 = blockIdx.x << 6;
    const int e = tid & 63, tg = tid >> 6;

    sW3[tid] = W3[tid];
    sW3[tid + 256] = W3[tid + 256];

    float acc[4] = {0.f, 0.f, 0.f, 0.f};

    for (int dc = 0; dc < 512; dc += 64) {
        __syncthreads();
#pragma unroll
        for (int i = 0; i < 4; i++) {
            int q = tid + (i << 8);
            int er = q >> 4, d4 = (q & 15) << 2;
            float4 v = *(const float4*)&g_h1[(long)(b * 256 + e0 + er) * 512 + dc + d4];
            sh1[(d4 + 0) * 65 + er] = v.x;
            sh1[(d4 + 1) * 65 + er] = v.y;
            sh1[(d4 + 2) * 65 + er] = v.z;
            sh1[(d4 + 3) * 65 + er] = v.w;
        }
        {
            int tt = tid >> 4, d4 = (tid & 15) << 2;
            float4 v = *(const float4*)&g_h2[(long)(b * 256 + t0 + tt) * 512 + dc + d4];
            *(float4*)&sh2[tt * 64 + d4] = v;
        }
        __syncthreads();

#pragma unroll 8
        for (int d = 0; d < 64; d++) {
            float h1v = sh1[d * 65 + e];
            float w = sW3[dc + d];
#pragma unroll
            for (int i = 0; i < 4; i++) {
                float v = h1v + sh2[(tg * 4 + i) * 64 + d];
                acc[i] += fast_tanh(v) * w;
            }
        }
    }

#pragma unroll
    for (int i = 0; i < 4; i++)
        g_scores[(long)(b * 256 + t0 + tg * 4 + i) * 256 + e0 + e] = acc[i];
}

// ----------------------------- row softmax (in place) -----------------------
__global__ void __launch_bounds__(256) softmax_kernel()
{
    float* p = g_scores + (long)blockIdx.x * 256;
    const int tid = threadIdx.x;
    const int lane = tid & 31, w = tid >> 5;
    __shared__ float redm[8];
    __shared__ float reds[8];

    float v = p[tid];
    float m = v;
#pragma unroll
    for (int o = 16; o; o >>= 1) m = fmaxf(m, __shfl_xor_sync(0xffffffffu, m, o));
    if (lane == 0) redm[w] = m;
    __syncthreads();
    if (tid < 32) {
        float x = (tid < 8) ? redm[tid] : -1e30f;
#pragma unroll
        for (int o = 4; o; o >>= 1) x = fmaxf(x, __shfl_xor_sync(0xffffffffu, x, o));
        if (tid == 0) redm[0] = x;
    }
    __syncthreads();
    float ev = __expf(v - redm[0]);
    float ssum = ev;
#pragma unroll
    for (int o = 16; o; o >>= 1) ssum += __shfl_xor_sync(0xffffffffu, ssum, o);
    if (lane == 0) reds[w] = ssum;
    __syncthreads();
    if (tid < 32) {
        float x = (tid < 8) ? reds[tid] : 0.f;
#pragma unroll
        for (int o = 4; o; o >>= 1) x += __shfl_xor_sync(0xffffffffu, x, o);
        if (tid == 0) reds[0] = x;
    }
    __syncthreads();
    p[tid] = ev / reds[0];
}

// ----------------------------- launch ---------------------------------------
extern "C" void kernel_launch(void* const* d_in, const int* in_sizes, int n_in,
                              void* d_out, int out_size)
{
    const float* inputs   = (const float*)d_in[0];
    const float* attended = (const float*)d_in[1];
    const float* Wk       = (const float*)d_in[2];
    const float* Wr       = (const float*)d_in[3];
    const float* lstm_b   = (const float*)d_in[4];
    const float* W1       = (const float*)d_in[5];
    const float* b1       = (const float*)d_in[6];
    const float* W3       = (const float*)d_in[7];
    /* b3 (d_in[8]) cancels in softmax */
    const float* Wout     = (const float*)d_in[9];
    const float* bout     = (const float*)d_in[10];
    float* dout = (float*)d_out;

    static float* pXg = nullptr;
    static float* pH1 = nullptr;
    static float* pH2 = nullptr;
    static float* pXC = nullptr;
    static float* pSc = nullptr;
    static float* pPt = nullptr;
    static bool attr_done = false;
    if (!pXg) {
        cudaGetSymbolAddress((void**)&pXg, g_Xg);
        cudaGetSymbolAddress((void**)&pH1, g_h1);
        cudaGetSymbolAddress((void**)&pH2, g_h2);
        cudaGetSymbolAddress((void**)&pXC, g_XC);
        cudaGetSymbolAddress((void**)&pSc, g_scores);
        cudaGetSymbolAddress((void**)&pPt, g_part);
    }
    if (!attr_done) {
        cudaFuncSetAttribute(lstm_kernel, cudaFuncAttributeMaxDynamicSharedMemorySize, 50176);
        attr_done = true;
    }
    const long PS = (long)ROWS * D;   // partial stride (1M floats)

    // 1. Xg = inputs @ Wk + lstm_b              [2048,2048] K=80
    sgemm128<<<dim3(32, 16, 1), 256>>>(inputs, DIN, 0, Wk, 4 * D, 0,
                                       pXg, 4 * D, 0, ROWS, 4 * D, DIN, lstm_b);
    // 2. h1 = attended @ W1 + b1  (split-K 2)
    sgemm128<<<dim3(8, 16, 2), 256>>>(attended, D, 256, W1, D, 256L * D,
                                      pPt, D, PS, ROWS, D, 256, nullptr);
    reduce_parts<<<PS / 1024, 256>>>(pPt, PS, 2, b1, D, pH1, (int)PS);
    // 3. LSTM (persistent; writes x into g_XC[:, :512] and states into dout)
    lstm_kernel<<<NBLK_LSTM, 256, 50176>>>(Wr, dout);
    // 4. h2 = x @ W1 + b1  (split-K 2)
    sgemm128<<<dim3(8, 16, 2), 256>>>(pXC, 2 * D, 256, W1, D, 256L * D,
                                      pPt, D, PS, ROWS, D, 256, nullptr);
    reduce_parts<<<PS / 1024, 256>>>(pPt, PS, 2, b1, D, pH2, (int)PS);
    // 5. scores
    scores_kernel<<<dim3(4, 16, 8), 256>>>(W3);
    // 6. softmax (in place -> attn)
    softmax_kernel<<<ROWS, 256>>>();
    // 7. weighted = attn @ attended  (batched over z) -> g_XC[:, 512:]
    sgemm128<<<dim3(8, 2, 8), 256>>>(pSc, TE, (long)TD * TE,
                                     attended, D, (long)TE * D,
                                     pXC + D, 2 * D, (long)TD * 2 * D,
                                     TD, D, TE, nullptr);
    // 8. out = [x | weighted] @ Wout + bout  (split-K 4)
    {
        const long OS = (long)ROWS * MEL;   // 163840
        sgemm128<<<dim3(2, 16, 4), 256>>>(pXC, 2 * D, 256, Wout, MEL, 256L * MEL,
                                          pPt, MEL, OS, ROWS, MEL, 256, nullptr);
        reduce_parts<<<(unsigned)(OS / 1024), 256>>>(pPt, OS, 4, bout, MEL, dout, (int)OS);
    }
}